// round 10
// baseline (speedup 1.0000x reference)
#include <cuda_runtime.h>
#include <cuda_bf16.h>
#include <math.h>
#include <limits.h>

#define NN 50000
#define EE 800000
#define MM 3
#define IN_ 256
#define HID_ 16
#define HEADS_ 8
#define HD_ 128
#define OUT_ 8
#define NTASK (MM * NN)
#define CAP 32
#define GEMM_BLKS ((NN + 127) / 128)          // 391
#define PSCAN_BLKS ((NN + 1023) / 1024)       // 49 per path

// ---------------- scratch ----------------
__device__ __nv_bfloat16 g_featb[MM * NN * HD_];
__device__ float g_z[MM * NN * HD_];
__device__ float g_el[MM * NN * HEADS_];
__device__ float g_er[MM * NN * HEADS_];
__device__ int   g_deg[NTASK];
__device__ int   g_off[NTASK];
__device__ int   g_cur[NTASK];
__device__ int   g_csr[MM * EE];
__device__ int   g_bsum[MM][64];
__device__ float g_wsum[MM];
__device__ float g_pz[MM * HD_];

__device__ __forceinline__ unsigned cvt_tf32(float x) {
    unsigned r;
    asm("cvt.rna.tf32.f32 %0, %1;" : "=r"(r) : "f"(x));
    return r;
}
__device__ __forceinline__ void mma_tf32(float* c, const unsigned* a,
                                         unsigned b0, unsigned b1) {
    asm("mma.sync.aligned.m16n8k8.row.col.f32.tf32.tf32.f32 "
        "{%0,%1,%2,%3},{%4,%5,%6,%7},{%8,%9},{%0,%1,%2,%3};"
        : "+f"(c[0]), "+f"(c[1]), "+f"(c[2]), "+f"(c[3])
        : "r"(a[0]), "r"(a[1]), "r"(a[2]), "r"(a[3]), "r"(b0), "r"(b1));
}
__device__ __forceinline__ float tanh_fast(float x) {
    x = fminf(fmaxf(x, -15.f), 15.f);
    float e = __expf(2.f * x);
    return __fdividef(e - 1.f, e + 1.f);
}

// ---------------- GEMM path p: feat(bf16) = h @ fc_w[p], fused el/er ----------------
__global__ __launch_bounds__(256) void k_gemm(
        const float* __restrict__ h, const float* __restrict__ W,
        const float* __restrict__ al, const float* __restrict__ ar, int p) {
    __shared__ unsigned As[128][33];
    __shared__ unsigned Bs[32][132];
    int tid = threadIdx.x;
    int row0 = blockIdx.x * 128;
    int w = tid >> 5, t = tid & 31;
    int mrow = (w & 3) * 32;
    int ncol = (w >> 2) * 64;
    const float* Wp = W + (size_t)p * IN_ * HD_;

    float acc[2][8][4];
#pragma unroll
    for (int mf = 0; mf < 2; mf++)
#pragma unroll
        for (int nf = 0; nf < 8; nf++)
#pragma unroll
            for (int k = 0; k < 4; k++) acc[mf][nf][k] = 0.f;

    for (int kk = 0; kk < IN_; kk += 32) {
#pragma unroll
        for (int j = 0; j < 4; j++) {
            int idx = tid + 256 * j;
            int r = idx >> 3;
            int c = (idx & 7) * 4;
            float4 v = make_float4(0.f, 0.f, 0.f, 0.f);
            if (row0 + r < NN)
                v = *(const float4*)&h[(size_t)(row0 + r) * IN_ + kk + c];
            As[r][c] = cvt_tf32(v.x); As[r][c + 1] = cvt_tf32(v.y);
            As[r][c + 2] = cvt_tf32(v.z); As[r][c + 3] = cvt_tf32(v.w);
        }
#pragma unroll
        for (int j = 0; j < 4; j++) {
            int idx = tid + 256 * j;
            int r = idx >> 5;
            int c = (idx & 31) * 4;
            float4 v = *(const float4*)&Wp[(size_t)(kk + r) * HD_ + c];
            Bs[r][c] = cvt_tf32(v.x); Bs[r][c + 1] = cvt_tf32(v.y);
            Bs[r][c + 2] = cvt_tf32(v.z); Bs[r][c + 3] = cvt_tf32(v.w);
        }
        __syncthreads();
#pragma unroll
        for (int ks = 0; ks < 32; ks += 8) {
            unsigned a[2][4];
#pragma unroll
            for (int mf = 0; mf < 2; mf++) {
                int r = mrow + mf * 16 + (t >> 2);
                int kc = ks + (t & 3);
                a[mf][0] = As[r][kc];
                a[mf][1] = As[r + 8][kc];
                a[mf][2] = As[r][kc + 4];
                a[mf][3] = As[r + 8][kc + 4];
            }
#pragma unroll
            for (int nf = 0; nf < 8; nf++) {
                int col = ncol + nf * 8 + (t >> 2);
                int kc = ks + (t & 3);
                unsigned b0 = Bs[kc][col];
                unsigned b1 = Bs[kc + 4][col];
                mma_tf32(acc[0][nf], a[0], b0, b1);
                mma_tf32(acc[1][nf], a[1], b0, b1);
            }
        }
        __syncthreads();
    }

    int headbase = (w >> 2) * 4;
    size_t pn = (size_t)p * NN;
#pragma unroll
    for (int mf = 0; mf < 2; mf++) {
        int ra = row0 + mrow + mf * 16 + (t >> 2);
        int rb = ra + 8;
#pragma unroll
        for (int nf = 0; nf < 8; nf++) {
            int col = ncol + nf * 8 + (t & 3) * 2;
            if (ra < NN)
                *(__nv_bfloat162*)&g_featb[(pn + ra) * HD_ + col] =
                    __float22bfloat162_rn(make_float2(acc[mf][nf][0], acc[mf][nf][1]));
            if (rb < NN)
                *(__nv_bfloat162*)&g_featb[(pn + rb) * HD_ + col] =
                    __float22bfloat162_rn(make_float2(acc[mf][nf][2], acc[mf][nf][3]));
        }
#pragma unroll
        for (int hh = 0; hh < 4; hh++) {
            float sAl = 0.f, sBl = 0.f, sAr = 0.f, sBr = 0.f;
#pragma unroll
            for (int q = 0; q < 2; q++) {
                int nf = hh * 2 + q;
                int col = ncol + nf * 8 + (t & 3) * 2;
                float al0 = al[(size_t)p * HD_ + col], al1 = al[(size_t)p * HD_ + col + 1];
                float ar0 = ar[(size_t)p * HD_ + col], ar1 = ar[(size_t)p * HD_ + col + 1];
                sAl += acc[mf][nf][0] * al0 + acc[mf][nf][1] * al1;
                sBl += acc[mf][nf][2] * al0 + acc[mf][nf][3] * al1;
                sAr += acc[mf][nf][0] * ar0 + acc[mf][nf][1] * ar1;
                sBr += acc[mf][nf][2] * ar0 + acc[mf][nf][3] * ar1;
            }
            sAl += __shfl_xor_sync(0xffffffffu, sAl, 1);
            sAl += __shfl_xor_sync(0xffffffffu, sAl, 2);
            sBl += __shfl_xor_sync(0xffffffffu, sBl, 1);
            sBl += __shfl_xor_sync(0xffffffffu, sBl, 2);
            sAr += __shfl_xor_sync(0xffffffffu, sAr, 1);
            sAr += __shfl_xor_sync(0xffffffffu, sAr, 2);
            sBr += __shfl_xor_sync(0xffffffffu, sBr, 1);
            sBr += __shfl_xor_sync(0xffffffffu, sBr, 2);
            if ((t & 3) == 0) {
                if (ra < NN) {
                    g_el[(pn + ra) * HEADS_ + headbase + hh] = sAl;
                    g_er[(pn + ra) * HEADS_ + headbase + hh] = sAr;
                }
                if (rb < NN) {
                    g_el[(pn + rb) * HEADS_ + headbase + hh] = sBl;
                    g_er[(pn + rb) * HEADS_ + headbase + hh] = sBr;
                }
            }
        }
    }
}

// ---------------- per-path CSR build ----------------
__global__ void k_count(const int* __restrict__ edges, int p) {
    int e = blockIdx.x * blockDim.x + threadIdx.x;
    if (e >= EE) return;
    int dst = edges[(size_t)p * 2 * EE + EE + e];
    atomicAdd(&g_deg[p * NN + dst], 1);
}

__global__ __launch_bounds__(1024) void k_scan1(int p) {
    __shared__ int wsum[32];
    int tid = threadIdx.x, lane = tid & 31, wid = tid >> 5;
    int i = blockIdx.x * 1024 + tid;
    int v = (i < NN) ? g_deg[p * NN + i] : 0;
    int x = v;
#pragma unroll
    for (int off = 1; off < 32; off <<= 1) {
        int y = __shfl_up_sync(0xffffffffu, x, off);
        if (lane >= off) x += y;
    }
    if (lane == 31) wsum[wid] = x;
    __syncthreads();
    if (wid == 0) {
        int s = wsum[lane];
#pragma unroll
        for (int off = 1; off < 32; off <<= 1) {
            int y = __shfl_up_sync(0xffffffffu, s, off);
            if (lane >= off) s += y;
        }
        wsum[lane] = s;
    }
    __syncthreads();
    int prefix = (wid ? wsum[wid - 1] : 0) + x - v;
    if (i < NN) g_off[p * NN + i] = prefix;
    if (tid == 1023) g_bsum[p][blockIdx.x] = wsum[31];
}

__global__ void k_scan2(int p) {
    __shared__ int s[PSCAN_BLKS];
    int tid = threadIdx.x;
    if (tid < PSCAN_BLKS) s[tid] = g_bsum[p][tid];
    __syncthreads();
    if (tid == 0) {
        int run = 0;
        for (int k = 0; k < PSCAN_BLKS; k++) {
            int t = s[k];
            s[k] = run;
            run += t;
        }
    }
    __syncthreads();
    if (tid < PSCAN_BLKS) g_bsum[p][tid] = s[tid];
}

__global__ __launch_bounds__(1024) void k_scan3(int p) {
    int i = blockIdx.x * 1024 + threadIdx.x;
    if (i < NN) {
        int o = g_off[p * NN + i] + g_bsum[p][blockIdx.x] + p * EE;
        g_off[p * NN + i] = o;
        g_cur[p * NN + i] = o;
    }
}

__global__ void k_scatter(const int* __restrict__ edges, int p) {
    int e = blockIdx.x * blockDim.x + threadIdx.x;
    if (e >= EE) return;
    const int* eb = edges + (size_t)p * 2 * EE;
    int src = eb[e], dst = eb[EE + e];
    int pos = atomicAdd(&g_cur[p * NN + dst], 1);
    g_csr[pos] = src;
}

// ---------------- fused edge softmax + aggregation + elu (path p) ----------------
__global__ void k_agg(int p) {
    __shared__ float sm_v[8][CAP * 8];
    __shared__ int   sm_src[8][CAP];
    int warp = threadIdx.x >> 5, lane = threadIdx.x & 31;
    int n = blockIdx.x * 8 + warp;
    if (n >= NN) return;
    int t = p * NN + n;
    int deg = g_deg[t];
    int base = g_off[t];

    if (deg == 0) {
        *(float4*)&g_z[(size_t)t * HD_ + lane * 4] = make_float4(0.f, 0.f, 0.f, 0.f);
        return;
    }

    int hA = lane & 7;
    int eSub = lane >> 3;
    int hB = lane >> 2;

    float er_l = 0.f;
    if (lane < 8) er_l = g_er[(size_t)t * HEADS_ + lane];
    float er_hA = __shfl_sync(0xffffffffu, er_l, hA);

    float s = 0.f;
    float4 acc = make_float4(0.f, 0.f, 0.f, 0.f);

    for (int c0 = 0; c0 < deg; c0 += CAP) {
        int cn = min(CAP, deg - c0);
        float cs = 0.f;
        for (int e = eSub; e < cn; e += 4) {
            int src = g_csr[base + c0 + e];
            if (hA == 0) sm_src[warp][e] = src;
            float v = g_el[((size_t)p * NN + src) * HEADS_ + hA] + er_hA;
            v = v > 0.f ? v : 0.2f * v;
            float ex = __expf(v);
            sm_v[warp][e * 8 + hA] = ex;
            cs += ex;
        }
        cs += __shfl_xor_sync(0xffffffffu, cs, 8);
        cs += __shfl_xor_sync(0xffffffffu, cs, 16);
        s += cs;
        __syncwarp();
#pragma unroll 4
        for (int e = 0; e < cn; e++) {
            int src = sm_src[warp][e];
            float ex = sm_v[warp][e * 8 + hB];
            uint2 fv = *(const uint2*)&g_featb[((size_t)p * NN + src) * HD_ + lane * 4];
            float2 f0 = __bfloat1622float2(*reinterpret_cast<__nv_bfloat162*>(&fv.x));
            float2 f1 = __bfloat1622float2(*reinterpret_cast<__nv_bfloat162*>(&fv.y));
            acc.x += ex * f0.x; acc.y += ex * f0.y;
            acc.z += ex * f1.x; acc.w += ex * f1.y;
        }
        __syncwarp();
    }

    float sB = __shfl_sync(0xffffffffu, s, hB);
    float inv = 1.f / sB;
    float zx = acc.x * inv, zy = acc.y * inv, zz = acc.z * inv, zw = acc.w * inv;
    zx = zx > 0.f ? zx : expm1f(zx);
    zy = zy > 0.f ? zy : expm1f(zy);
    zz = zz > 0.f ? zz : expm1f(zz);
    zw = zw > 0.f ? zw : expm1f(zw);
    *(float4*)&g_z[(size_t)t * HD_ + lane * 4] = make_float4(zx, zy, zz, zw);
}

// ------- fused structure attention + node-softmax accumulation (path p) -------
__global__ __launch_bounds__(256) void k_wbeta(
        const float* __restrict__ W1, const float* __restrict__ b1,
        const float* __restrict__ w2, int mpath) {
    __shared__ unsigned As[128][33];
    __shared__ unsigned Bs[32][132];
    __shared__ float sw[128][2];
    __shared__ float spv[128];
    int row0 = blockIdx.x * 128;
    int tid = threadIdx.x;
    int w = tid >> 5, t = tid & 31;
    int mrow = (w & 3) * 32;
    int ncol = (w >> 2) * 64;
    int half = w >> 2;

    float acc[2][8][4];
#pragma unroll
    for (int nf = 0; nf < 8; nf++) {
        int col = ncol + nf * 8 + (t & 3) * 2;
        float b0 = b1[col], b1v = b1[col + 1];
#pragma unroll
        for (int mf = 0; mf < 2; mf++) {
            acc[mf][nf][0] = b0; acc[mf][nf][1] = b1v;
            acc[mf][nf][2] = b0; acc[mf][nf][3] = b1v;
        }
    }

    for (int kk = 0; kk < HD_; kk += 32) {
#pragma unroll
        for (int j = 0; j < 4; j++) {
            int idx = tid + 256 * j;
            int r = idx >> 3;
            int c = (idx & 7) * 4;
            float4 v = make_float4(0.f, 0.f, 0.f, 0.f);
            if (row0 + r < NN)
                v = *(const float4*)&g_z[((size_t)mpath * NN + row0 + r) * HD_ + kk + c];
            As[r][c] = cvt_tf32(v.x); As[r][c + 1] = cvt_tf32(v.y);
            As[r][c + 2] = cvt_tf32(v.z); As[r][c + 3] = cvt_tf32(v.w);
        }
#pragma unroll
        for (int j = 0; j < 4; j++) {
            int idx = tid + 256 * j;
            int r = idx >> 5;
            int c = (idx & 31) * 4;
            float4 v = *(const float4*)&W1[(size_t)(kk + r) * HD_ + c];
            Bs[r][c] = cvt_tf32(v.x); Bs[r][c + 1] = cvt_tf32(v.y);
            Bs[r][c + 2] = cvt_tf32(v.z); Bs[r][c + 3] = cvt_tf32(v.w);
        }
        __syncthreads();
#pragma unroll
        for (int ks = 0; ks < 32; ks += 8) {
            unsigned a[2][4];
#pragma unroll
            for (int mf = 0; mf < 2; mf++) {
                int r = mrow + mf * 16 + (t >> 2);
                int kc = ks + (t & 3);
                a[mf][0] = As[r][kc];
                a[mf][1] = As[r + 8][kc];
                a[mf][2] = As[r][kc + 4];
                a[mf][3] = As[r + 8][kc + 4];
            }
#pragma unroll
            for (int nf = 0; nf < 8; nf++) {
                int col = ncol + nf * 8 + (t >> 2);
                int kc = ks + (t & 3);
                unsigned b0 = Bs[kc][col];
                unsigned b1f = Bs[kc + 4][col];
                mma_tf32(acc[0][nf], a[0], b0, b1f);
                mma_tf32(acc[1][nf], a[1], b0, b1f);
            }
        }
        __syncthreads();
    }

#pragma unroll
    for (int mf = 0; mf < 2; mf++) {
        int lra = mrow + mf * 16 + (t >> 2);
        float tA = 0.f, tB = 0.f;
#pragma unroll
        for (int nf = 0; nf < 8; nf++) {
            int col = ncol + nf * 8 + (t & 3) * 2;
            float w0 = w2[col], w1v = w2[col + 1];
            tA += tanh_fast(acc[mf][nf][0]) * w0 + tanh_fast(acc[mf][nf][1]) * w1v;
            tB += tanh_fast(acc[mf][nf][2]) * w0 + tanh_fast(acc[mf][nf][3]) * w1v;
        }
        tA += __shfl_xor_sync(0xffffffffu, tA, 1);
        tA += __shfl_xor_sync(0xffffffffu, tA, 2);
        tB += __shfl_xor_sync(0xffffffffu, tB, 1);
        tB += __shfl_xor_sync(0xffffffffu, tB, 2);
        if ((t & 3) == 0) {
            sw[lra][half] = tA;
            sw[lra + 8][half] = tB;
        }
    }
    __syncthreads();
    if (tid < 128) {
        float wv = sw[tid][0] + sw[tid][1];
        spv[tid] = (row0 + tid < NN) ? __expf(wv) : 0.f;
    }
    __syncthreads();

    float4 a4 = make_float4(0.f, 0.f, 0.f, 0.f);
    float ws = 0.f;
#pragma unroll
    for (int r = 0; r < 16; r++) {
        int lr = w * 16 + r;
        int gr = row0 + lr;
        float pv = spv[lr];
        if (gr < NN) {
            float4 zv = *(const float4*)&g_z[((size_t)mpath * NN + gr) * HD_ + t * 4];
            a4.x += pv * zv.x; a4.y += pv * zv.y;
            a4.z += pv * zv.z; a4.w += pv * zv.w;
            ws += pv;
        }
    }
    float* o = &g_pz[mpath * HD_ + t * 4];
    asm volatile("red.global.add.v4.f32 [%0], {%1,%2,%3,%4};"
                 :: "l"(o), "f"(a4.x), "f"(a4.y), "f"(a4.z), "f"(a4.w)
                 : "memory");
    if (t == 0) atomicAdd(&g_wsum[mpath], ws);
}

__global__ void k_final(const float* __restrict__ pred_w, const float* __restrict__ pred_b,
                        float* __restrict__ out) {
    int t = threadIdx.x;
    if (t < MM * OUT_) {
        int m = t / OUT_, o = t - m * OUT_;
        float inv = 1.f / g_wsum[m];
        float s = pred_b[o];
#pragma unroll 8
        for (int j = 0; j < HD_; j++)
            s += g_pz[m * HD_ + j] * inv * pred_w[(size_t)j * OUT_ + o];
        out[t] = s;
    }
}

// ---------------- launch: 2-stream per-path pipeline ----------------
extern "C" void kernel_launch(void* const* d_in, const int* in_sizes, int n_in,
                              void* d_out, int out_size) {
    const float* h      = (const float*)d_in[0];
    const int*   edges  = (const int*)d_in[1];
    const float* fc_w   = (const float*)d_in[2];
    const float* attn_l = (const float*)d_in[3];
    const float* attn_r = (const float*)d_in[4];
    const float* sa_w1  = (const float*)d_in[5];
    const float* sa_b1  = (const float*)d_in[6];
    const float* sa_w2  = (const float*)d_in[7];
    const float* pred_w = (const float*)d_in[8];
    const float* pred_b = (const float*)d_in[9];
    float* out = (float*)d_out;

    void *pdeg, *pwsum, *ppz;
    cudaGetSymbolAddress(&pdeg, g_deg);
    cudaGetSymbolAddress(&pwsum, g_wsum);
    cudaGetSymbolAddress(&ppz, g_pz);

    cudaStream_t s2;
    cudaStreamCreateWithFlags(&s2, cudaStreamNonBlocking);
    cudaEvent_t evFork, evC[MM], evA[MM], evJoin;
    cudaEventCreateWithFlags(&evFork, cudaEventDisableTiming);
    cudaEventCreateWithFlags(&evJoin, cudaEventDisableTiming);
    for (int p = 0; p < MM; p++) {
        cudaEventCreateWithFlags(&evC[p], cudaEventDisableTiming);
        cudaEventCreateWithFlags(&evA[p], cudaEventDisableTiming);
    }

    // main: small memsets, then fork
    cudaMemsetAsync(pwsum, 0, sizeof(float) * MM);
    cudaMemsetAsync(ppz, 0, sizeof(float) * MM * HD_);
    cudaEventRecord(evFork, 0);
    cudaStreamWaitEvent(s2, evFork, 0);

    int eblk = (EE + 255) / 256;
    // s2: CSR chains for all paths, event per path
    for (int p = 0; p < MM; p++) {
        cudaMemsetAsync((char*)pdeg + (size_t)p * NN * sizeof(int), 0,
                        sizeof(int) * NN, s2);
        k_count<<<eblk, 256, 0, s2>>>(edges, p);
        k_scan1<<<PSCAN_BLKS, 1024, 0, s2>>>(p);
        k_scan2<<<1, 64, 0, s2>>>(p);
        k_scan3<<<PSCAN_BLKS, 1024, 0, s2>>>(p);
        k_scatter<<<eblk, 256, 0, s2>>>(edges, p);
        cudaEventRecord(evC[p], s2);
    }

    // main: gemms (overlap CSR chains)
    for (int p = 0; p < MM; p++)
        k_gemm<<<GEMM_BLKS, 256>>>(h, fc_w, attn_l, attn_r, p);

    // main: agg(p); s2: wbeta(p) overlapping agg(p+1)
    for (int p = 0; p < MM; p++) {
        cudaStreamWaitEvent(0, evC[p], 0);
        k_agg<<<(NN + 7) / 8, 256>>>(p);
        cudaEventRecord(evA[p], 0);
        cudaStreamWaitEvent(s2, evA[p], 0);
        k_wbeta<<<GEMM_BLKS, 256, 0, s2>>>(sa_w1, sa_b1, sa_w2, p);
    }
    cudaEventRecord(evJoin, s2);
    cudaStreamWaitEvent(0, evJoin, 0);
    k_final<<<1, 32>>>(pred_w, pred_b, out);

    cudaEventDestroy(evFork);
    cudaEventDestroy(evJoin);
    for (int p = 0; p < MM; p++) {
        cudaEventDestroy(evC[p]);
        cudaEventDestroy(evA[p]);
    }
    cudaStreamDestroy(s2);
}

// round 11
// speedup vs baseline: 1.0717x; 1.0717x over previous
#include <cuda_runtime.h>
#include <cuda_bf16.h>
#include <math.h>
#include <limits.h>

#define NN 50000
#define EE 800000
#define MM 3
#define IN_ 256
#define HID_ 16
#define HEADS_ 8
#define HD_ 128
#define OUT_ 8
#define NTASK (MM * NN)
#define CAP 32
#define GEMM_BLKS ((NN + 127) / 128)          // 391
#define SCAN_BLKS ((NTASK + 1023) / 1024)     // 147

// ---------------- scratch ----------------
__device__ __nv_bfloat16 g_featb[MM * NN * HD_];
__device__ float g_z[MM * NN * HD_];
__device__ float g_el[MM * NN * HEADS_];
__device__ float g_er[MM * NN * HEADS_];
__device__ int   g_deg[NTASK];
__device__ int   g_off[NTASK];
__device__ int   g_cur[NTASK];
__device__ int   g_csr[MM * EE];
__device__ int   g_bsum[SCAN_BLKS];
__device__ float g_wsum[MM];
__device__ float g_pz[MM * HD_];

__device__ __forceinline__ unsigned cvt_tf32(float x) {
    unsigned r;
    asm("cvt.rna.tf32.f32 %0, %1;" : "=r"(r) : "f"(x));
    return r;
}
__device__ __forceinline__ void mma_tf32(float* c, const unsigned* a,
                                         unsigned b0, unsigned b1) {
    asm("mma.sync.aligned.m16n8k8.row.col.f32.tf32.tf32.f32 "
        "{%0,%1,%2,%3},{%4,%5,%6,%7},{%8,%9},{%0,%1,%2,%3};"
        : "+f"(c[0]), "+f"(c[1]), "+f"(c[2]), "+f"(c[3])
        : "r"(a[0]), "r"(a[1]), "r"(a[2]), "r"(a[3]), "r"(b0), "r"(b1));
}
__device__ __forceinline__ float tanh_fast(float x) {
    x = fminf(fmaxf(x, -15.f), 15.f);
    float e = __expf(2.f * x);
    return __fdividef(e - 1.f, e + 1.f);
}

// ---------------- GEMM (all paths): feat(bf16) = h @ fc_w[p], fused el/er ----------------
__global__ __launch_bounds__(256) void k_gemm(
        const float* __restrict__ h, const float* __restrict__ W,
        const float* __restrict__ al, const float* __restrict__ ar) {
    __shared__ unsigned As[128][33];
    __shared__ unsigned Bs[32][132];
    int tid = threadIdx.x;
    int p = blockIdx.y;
    int row0 = blockIdx.x * 128;
    int w = tid >> 5, t = tid & 31;
    int mrow = (w & 3) * 32;
    int ncol = (w >> 2) * 64;
    const float* Wp = W + (size_t)p * IN_ * HD_;

    float acc[2][8][4];
#pragma unroll
    for (int mf = 0; mf < 2; mf++)
#pragma unroll
        for (int nf = 0; nf < 8; nf++)
#pragma unroll
            for (int k = 0; k < 4; k++) acc[mf][nf][k] = 0.f;

    for (int kk = 0; kk < IN_; kk += 32) {
#pragma unroll
        for (int j = 0; j < 4; j++) {
            int idx = tid + 256 * j;
            int r = idx >> 3;
            int c = (idx & 7) * 4;
            float4 v = make_float4(0.f, 0.f, 0.f, 0.f);
            if (row0 + r < NN)
                v = *(const float4*)&h[(size_t)(row0 + r) * IN_ + kk + c];
            As[r][c] = cvt_tf32(v.x); As[r][c + 1] = cvt_tf32(v.y);
            As[r][c + 2] = cvt_tf32(v.z); As[r][c + 3] = cvt_tf32(v.w);
        }
#pragma unroll
        for (int j = 0; j < 4; j++) {
            int idx = tid + 256 * j;
            int r = idx >> 5;
            int c = (idx & 31) * 4;
            float4 v = *(const float4*)&Wp[(size_t)(kk + r) * HD_ + c];
            Bs[r][c] = cvt_tf32(v.x); Bs[r][c + 1] = cvt_tf32(v.y);
            Bs[r][c + 2] = cvt_tf32(v.z); Bs[r][c + 3] = cvt_tf32(v.w);
        }
        __syncthreads();
#pragma unroll
        for (int ks = 0; ks < 32; ks += 8) {
            unsigned a[2][4];
#pragma unroll
            for (int mf = 0; mf < 2; mf++) {
                int r = mrow + mf * 16 + (t >> 2);
                int kc = ks + (t & 3);
                a[mf][0] = As[r][kc];
                a[mf][1] = As[r + 8][kc];
                a[mf][2] = As[r][kc + 4];
                a[mf][3] = As[r + 8][kc + 4];
            }
#pragma unroll
            for (int nf = 0; nf < 8; nf++) {
                int col = ncol + nf * 8 + (t >> 2);
                int kc = ks + (t & 3);
                unsigned b0 = Bs[kc][col];
                unsigned b1 = Bs[kc + 4][col];
                mma_tf32(acc[0][nf], a[0], b0, b1);
                mma_tf32(acc[1][nf], a[1], b0, b1);
            }
        }
        __syncthreads();
    }

    int headbase = (w >> 2) * 4;
    size_t pn = (size_t)p * NN;
#pragma unroll
    for (int mf = 0; mf < 2; mf++) {
        int ra = row0 + mrow + mf * 16 + (t >> 2);
        int rb = ra + 8;
#pragma unroll
        for (int nf = 0; nf < 8; nf++) {
            int col = ncol + nf * 8 + (t & 3) * 2;
            if (ra < NN)
                *(__nv_bfloat162*)&g_featb[(pn + ra) * HD_ + col] =
                    __float22bfloat162_rn(make_float2(acc[mf][nf][0], acc[mf][nf][1]));
            if (rb < NN)
                *(__nv_bfloat162*)&g_featb[(pn + rb) * HD_ + col] =
                    __float22bfloat162_rn(make_float2(acc[mf][nf][2], acc[mf][nf][3]));
        }
#pragma unroll
        for (int hh = 0; hh < 4; hh++) {
            float sAl = 0.f, sBl = 0.f, sAr = 0.f, sBr = 0.f;
#pragma unroll
            for (int q = 0; q < 2; q++) {
                int nf = hh * 2 + q;
                int col = ncol + nf * 8 + (t & 3) * 2;
                float al0 = al[(size_t)p * HD_ + col], al1 = al[(size_t)p * HD_ + col + 1];
                float ar0 = ar[(size_t)p * HD_ + col], ar1 = ar[(size_t)p * HD_ + col + 1];
                sAl += acc[mf][nf][0] * al0 + acc[mf][nf][1] * al1;
                sBl += acc[mf][nf][2] * al0 + acc[mf][nf][3] * al1;
                sAr += acc[mf][nf][0] * ar0 + acc[mf][nf][1] * ar1;
                sBr += acc[mf][nf][2] * ar0 + acc[mf][nf][3] * ar1;
            }
            sAl += __shfl_xor_sync(0xffffffffu, sAl, 1);
            sAl += __shfl_xor_sync(0xffffffffu, sAl, 2);
            sBl += __shfl_xor_sync(0xffffffffu, sBl, 1);
            sBl += __shfl_xor_sync(0xffffffffu, sBl, 2);
            sAr += __shfl_xor_sync(0xffffffffu, sAr, 1);
            sAr += __shfl_xor_sync(0xffffffffu, sAr, 2);
            sBr += __shfl_xor_sync(0xffffffffu, sBr, 1);
            sBr += __shfl_xor_sync(0xffffffffu, sBr, 2);
            if ((t & 3) == 0) {
                if (ra < NN) {
                    g_el[(pn + ra) * HEADS_ + headbase + hh] = sAl;
                    g_er[(pn + ra) * HEADS_ + headbase + hh] = sAr;
                }
                if (rb < NN) {
                    g_el[(pn + rb) * HEADS_ + headbase + hh] = sBl;
                    g_er[(pn + rb) * HEADS_ + headbase + hh] = sBr;
                }
            }
        }
    }
}

// ---------------- CSR build (whole graph) ----------------
__global__ void k_count(const int* __restrict__ edges) {
    int idx = blockIdx.x * blockDim.x + threadIdx.x;
    if (idx >= MM * EE) return;
    int p = idx / EE, e = idx - p * EE;
    int dst = edges[(size_t)p * 2 * EE + EE + e];
    atomicAdd(&g_deg[p * NN + dst], 1);
}

__global__ __launch_bounds__(1024) void k_scan1() {
    __shared__ int wsum[32];
    int tid = threadIdx.x, lane = tid & 31, wid = tid >> 5;
    int i = blockIdx.x * 1024 + tid;
    int v = (i < NTASK) ? g_deg[i] : 0;
    int x = v;
#pragma unroll
    for (int off = 1; off < 32; off <<= 1) {
        int y = __shfl_up_sync(0xffffffffu, x, off);
        if (lane >= off) x += y;
    }
    if (lane == 31) wsum[wid] = x;
    __syncthreads();
    if (wid == 0) {
        int s = wsum[lane];
#pragma unroll
        for (int off = 1; off < 32; off <<= 1) {
            int y = __shfl_up_sync(0xffffffffu, s, off);
            if (lane >= off) s += y;
        }
        wsum[lane] = s;
    }
    __syncthreads();
    int prefix = (wid ? wsum[wid - 1] : 0) + x - v;
    if (i < NTASK) g_off[i] = prefix;
    if (tid == 1023) g_bsum[blockIdx.x] = wsum[31];
}

__global__ void k_scan2() {
    __shared__ int s[SCAN_BLKS];
    int tid = threadIdx.x;
    if (tid < SCAN_BLKS) s[tid] = g_bsum[tid];
    __syncthreads();
    if (tid == 0) {
        int run = 0;
        for (int k = 0; k < SCAN_BLKS; k++) {
            int t = s[k];
            s[k] = run;
            run += t;
        }
    }
    __syncthreads();
    if (tid < SCAN_BLKS) g_bsum[tid] = s[tid];
}

__global__ __launch_bounds__(1024) void k_scan3() {
    int i = blockIdx.x * 1024 + threadIdx.x;
    if (i < NTASK) {
        int o = g_off[i] + g_bsum[blockIdx.x];
        g_off[i] = o;
        g_cur[i] = o;
    }
}

__global__ void k_scatter(const int* __restrict__ edges) {
    int idx = blockIdx.x * blockDim.x + threadIdx.x;
    if (idx >= MM * EE) return;
    int p = idx / EE, e = idx - p * EE;
    const int* eb = edges + (size_t)p * 2 * EE;
    int src = eb[e], dst = eb[EE + e];
    int pos = atomicAdd(&g_cur[p * NN + dst], 1);
    g_csr[pos] = src;
}

// ---------------- fused edge softmax + aggregation + elu (path p) ----------------
__global__ void k_agg(int p) {
    __shared__ float sm_v[8][CAP * 8];
    __shared__ int   sm_src[8][CAP];
    int warp = threadIdx.x >> 5, lane = threadIdx.x & 31;
    int n = blockIdx.x * 8 + warp;
    if (n >= NN) return;
    int t = p * NN + n;
    int deg = g_deg[t];
    int base = g_off[t];

    if (deg == 0) {
        *(float4*)&g_z[(size_t)t * HD_ + lane * 4] = make_float4(0.f, 0.f, 0.f, 0.f);
        return;
    }

    int hA = lane & 7;
    int eSub = lane >> 3;
    int hB = lane >> 2;

    float er_l = 0.f;
    if (lane < 8) er_l = g_er[(size_t)t * HEADS_ + lane];
    float er_hA = __shfl_sync(0xffffffffu, er_l, hA);

    float s = 0.f;
    float4 acc = make_float4(0.f, 0.f, 0.f, 0.f);

    for (int c0 = 0; c0 < deg; c0 += CAP) {
        int cn = min(CAP, deg - c0);
        float cs = 0.f;
        for (int e = eSub; e < cn; e += 4) {
            int src = g_csr[base + c0 + e];
            if (hA == 0) sm_src[warp][e] = src;
            float v = g_el[((size_t)p * NN + src) * HEADS_ + hA] + er_hA;
            v = v > 0.f ? v : 0.2f * v;
            float ex = __expf(v);
            sm_v[warp][e * 8 + hA] = ex;
            cs += ex;
        }
        cs += __shfl_xor_sync(0xffffffffu, cs, 8);
        cs += __shfl_xor_sync(0xffffffffu, cs, 16);
        s += cs;
        __syncwarp();
#pragma unroll 4
        for (int e = 0; e < cn; e++) {
            int src = sm_src[warp][e];
            float ex = sm_v[warp][e * 8 + hB];
            uint2 fv = *(const uint2*)&g_featb[((size_t)p * NN + src) * HD_ + lane * 4];
            float2 f0 = __bfloat1622float2(*reinterpret_cast<__nv_bfloat162*>(&fv.x));
            float2 f1 = __bfloat1622float2(*reinterpret_cast<__nv_bfloat162*>(&fv.y));
            acc.x += ex * f0.x; acc.y += ex * f0.y;
            acc.z += ex * f1.x; acc.w += ex * f1.y;
        }
        __syncwarp();
    }

    float sB = __shfl_sync(0xffffffffu, s, hB);
    float inv = 1.f / sB;
    float zx = acc.x * inv, zy = acc.y * inv, zz = acc.z * inv, zw = acc.w * inv;
    zx = zx > 0.f ? zx : expm1f(zx);
    zy = zy > 0.f ? zy : expm1f(zy);
    zz = zz > 0.f ? zz : expm1f(zz);
    zw = zw > 0.f ? zw : expm1f(zw);
    *(float4*)&g_z[(size_t)t * HD_ + lane * 4] = make_float4(zx, zy, zz, zw);
}

// ------- fused structure attention + node-softmax accumulation (path p) -------
__global__ __launch_bounds__(256) void k_wbeta(
        const float* __restrict__ W1, const float* __restrict__ b1,
        const float* __restrict__ w2, int mpath) {
    __shared__ unsigned As[128][33];
    __shared__ unsigned Bs[32][132];
    __shared__ float sw[128][2];
    __shared__ float spv[128];
    int row0 = blockIdx.x * 128;
    int tid = threadIdx.x;
    int w = tid >> 5, t = tid & 31;
    int mrow = (w & 3) * 32;
    int ncol = (w >> 2) * 64;
    int half = w >> 2;

    float acc[2][8][4];
#pragma unroll
    for (int nf = 0; nf < 8; nf++) {
        int col = ncol + nf * 8 + (t & 3) * 2;
        float b0 = b1[col], b1v = b1[col + 1];
#pragma unroll
        for (int mf = 0; mf < 2; mf++) {
            acc[mf][nf][0] = b0; acc[mf][nf][1] = b1v;
            acc[mf][nf][2] = b0; acc[mf][nf][3] = b1v;
        }
    }

    for (int kk = 0; kk < HD_; kk += 32) {
#pragma unroll
        for (int j = 0; j < 4; j++) {
            int idx = tid + 256 * j;
            int r = idx >> 3;
            int c = (idx & 7) * 4;
            float4 v = make_float4(0.f, 0.f, 0.f, 0.f);
            if (row0 + r < NN)
                v = *(const float4*)&g_z[((size_t)mpath * NN + row0 + r) * HD_ + kk + c];
            As[r][c] = cvt_tf32(v.x); As[r][c + 1] = cvt_tf32(v.y);
            As[r][c + 2] = cvt_tf32(v.z); As[r][c + 3] = cvt_tf32(v.w);
        }
#pragma unroll
        for (int j = 0; j < 4; j++) {
            int idx = tid + 256 * j;
            int r = idx >> 5;
            int c = (idx & 31) * 4;
            float4 v = *(const float4*)&W1[(size_t)(kk + r) * HD_ + c];
            Bs[r][c] = cvt_tf32(v.x); Bs[r][c + 1] = cvt_tf32(v.y);
            Bs[r][c + 2] = cvt_tf32(v.z); Bs[r][c + 3] = cvt_tf32(v.w);
        }
        __syncthreads();
#pragma unroll
        for (int ks = 0; ks < 32; ks += 8) {
            unsigned a[2][4];
#pragma unroll
            for (int mf = 0; mf < 2; mf++) {
                int r = mrow + mf * 16 + (t >> 2);
                int kc = ks + (t & 3);
                a[mf][0] = As[r][kc];
                a[mf][1] = As[r + 8][kc];
                a[mf][2] = As[r][kc + 4];
                a[mf][3] = As[r + 8][kc + 4];
            }
#pragma unroll
            for (int nf = 0; nf < 8; nf++) {
                int col = ncol + nf * 8 + (t >> 2);
                int kc = ks + (t & 3);
                unsigned b0 = Bs[kc][col];
                unsigned b1f = Bs[kc + 4][col];
                mma_tf32(acc[0][nf], a[0], b0, b1f);
                mma_tf32(acc[1][nf], a[1], b0, b1f);
            }
        }
        __syncthreads();
    }

#pragma unroll
    for (int mf = 0; mf < 2; mf++) {
        int lra = mrow + mf * 16 + (t >> 2);
        float tA = 0.f, tB = 0.f;
#pragma unroll
        for (int nf = 0; nf < 8; nf++) {
            int col = ncol + nf * 8 + (t & 3) * 2;
            float w0 = w2[col], w1v = w2[col + 1];
            tA += tanh_fast(acc[mf][nf][0]) * w0 + tanh_fast(acc[mf][nf][1]) * w1v;
            tB += tanh_fast(acc[mf][nf][2]) * w0 + tanh_fast(acc[mf][nf][3]) * w1v;
        }
        tA += __shfl_xor_sync(0xffffffffu, tA, 1);
        tA += __shfl_xor_sync(0xffffffffu, tA, 2);
        tB += __shfl_xor_sync(0xffffffffu, tB, 1);
        tB += __shfl_xor_sync(0xffffffffu, tB, 2);
        if ((t & 3) == 0) {
            sw[lra][half] = tA;
            sw[lra + 8][half] = tB;
        }
    }
    __syncthreads();
    if (tid < 128) {
        float wv = sw[tid][0] + sw[tid][1];
        spv[tid] = (row0 + tid < NN) ? __expf(wv) : 0.f;
    }
    __syncthreads();

    float4 a4 = make_float4(0.f, 0.f, 0.f, 0.f);
    float ws = 0.f;
#pragma unroll
    for (int r = 0; r < 16; r++) {
        int lr = w * 16 + r;
        int gr = row0 + lr;
        float pv = spv[lr];
        if (gr < NN) {
            float4 zv = *(const float4*)&g_z[((size_t)mpath * NN + gr) * HD_ + t * 4];
            a4.x += pv * zv.x; a4.y += pv * zv.y;
            a4.z += pv * zv.z; a4.w += pv * zv.w;
            ws += pv;
        }
    }
    float* o = &g_pz[mpath * HD_ + t * 4];
    asm volatile("red.global.add.v4.f32 [%0], {%1,%2,%3,%4};"
                 :: "l"(o), "f"(a4.x), "f"(a4.y), "f"(a4.z), "f"(a4.w)
                 : "memory");
    if (t == 0) atomicAdd(&g_wsum[mpath], ws);
}

__global__ void k_final(const float* __restrict__ pred_w, const float* __restrict__ pred_b,
                        float* __restrict__ out) {
    int t = threadIdx.x;
    if (t < MM * OUT_) {
        int m = t / OUT_, o = t - m * OUT_;
        float inv = 1.f / g_wsum[m];
        float s = pred_b[o];
#pragma unroll 8
        for (int j = 0; j < HD_; j++)
            s += g_pz[m * HD_ + j] * inv * pred_w[(size_t)j * OUT_ + o];
        out[t] = s;
    }
}

// ------- launch: R7 skeleton + per-path agg/wbeta pipeline on 2 streams -------
extern "C" void kernel_launch(void* const* d_in, const int* in_sizes, int n_in,
                              void* d_out, int out_size) {
    const float* h      = (const float*)d_in[0];
    const int*   edges  = (const int*)d_in[1];
    const float* fc_w   = (const float*)d_in[2];
    const float* attn_l = (const float*)d_in[3];
    const float* attn_r = (const float*)d_in[4];
    const float* sa_w1  = (const float*)d_in[5];
    const float* sa_b1  = (const float*)d_in[6];
    const float* sa_w2  = (const float*)d_in[7];
    const float* pred_w = (const float*)d_in[8];
    const float* pred_b = (const float*)d_in[9];
    float* out = (float*)d_out;

    void *pdeg, *pwsum, *ppz;
    cudaGetSymbolAddress(&pdeg, g_deg);
    cudaGetSymbolAddress(&pwsum, g_wsum);
    cudaGetSymbolAddress(&ppz, g_pz);

    cudaStream_t s2;
    cudaStreamCreateWithFlags(&s2, cudaStreamNonBlocking);
    cudaEvent_t evFork, evJoin, evA[MM], evW;
    cudaEventCreateWithFlags(&evFork, cudaEventDisableTiming);
    cudaEventCreateWithFlags(&evJoin, cudaEventDisableTiming);
    cudaEventCreateWithFlags(&evW, cudaEventDisableTiming);
    for (int p = 0; p < MM; p++)
        cudaEventCreateWithFlags(&evA[p], cudaEventDisableTiming);

    // fork: whole-graph CSR chain on s2 (overlaps gemm on main)
    cudaEventRecord(evFork, 0);
    cudaStreamWaitEvent(s2, evFork, 0);

    cudaMemsetAsync(pdeg, 0, sizeof(int) * NTASK, s2);
    int et = MM * EE;
    k_count<<<(et + 255) / 256, 256, 0, s2>>>(edges);
    k_scan1<<<SCAN_BLKS, 1024, 0, s2>>>();
    k_scan2<<<1, 256, 0, s2>>>();
    k_scan3<<<SCAN_BLKS, 1024, 0, s2>>>();
    k_scatter<<<(et + 255) / 256, 256, 0, s2>>>(edges);
    cudaEventRecord(evJoin, s2);

    // main: memsets + whole gemm
    cudaMemsetAsync(pwsum, 0, sizeof(float) * MM);
    cudaMemsetAsync(ppz, 0, sizeof(float) * MM * HD_);
    dim3 gg(GEMM_BLKS, MM);
    k_gemm<<<gg, 256>>>(h, fc_w, attn_l, attn_r);

    // join CSR, then per-path agg on main, wbeta pipelined on s2
    cudaStreamWaitEvent(0, evJoin, 0);
    for (int p = 0; p < MM; p++) {
        k_agg<<<(NN + 7) / 8, 256>>>(p);
        cudaEventRecord(evA[p], 0);
        cudaStreamWaitEvent(s2, evA[p], 0);
        k_wbeta<<<GEMM_BLKS, 256, 0, s2>>>(sa_w1, sa_b1, sa_w2, p);
    }
    cudaEventRecord(evW, s2);
    cudaStreamWaitEvent(0, evW, 0);
    k_final<<<1, 32>>>(pred_w, pred_b, out);

    cudaEventDestroy(evFork);
    cudaEventDestroy(evJoin);
    cudaEventDestroy(evW);
    for (int p = 0; p < MM; p++) cudaEventDestroy(evA[p]);
    cudaStreamDestroy(s2);
}

// round 12
// speedup vs baseline: 1.1578x; 1.0803x over previous
#include <cuda_runtime.h>
#include <cuda_bf16.h>
#include <math.h>
#include <limits.h>

#define NN 50000
#define EE 800000
#define MM 3
#define IN_ 256
#define HID_ 16
#define HEADS_ 8
#define HD_ 128
#define OUT_ 8
#define NTASK (MM * NN)
#define GEMM_BLKS ((NN + 127) / 128)          // 391
#define SCAN_BLKS ((NTASK + 1023) / 1024)     // 147

// ---------------- scratch ----------------
__device__ __nv_bfloat16 g_featb[MM * NN * HD_];
__device__ float g_z[MM * NN * HD_];
__device__ float g_el[MM * NN * HEADS_];
__device__ float g_er[MM * NN * HEADS_];
__device__ int   g_deg[NTASK];
__device__ int   g_off[NTASK];
__device__ int   g_cur[NTASK];
__device__ int   g_csr[MM * EE];
__device__ int   g_bsum[SCAN_BLKS];
__device__ float g_wsum[MM];
__device__ float g_pz[MM * HD_];

__device__ __forceinline__ unsigned cvt_tf32(float x) {
    unsigned r;
    asm("cvt.rna.tf32.f32 %0, %1;" : "=r"(r) : "f"(x));
    return r;
}
__device__ __forceinline__ void mma_tf32(float* c, const unsigned* a,
                                         unsigned b0, unsigned b1) {
    asm("mma.sync.aligned.m16n8k8.row.col.f32.tf32.tf32.f32 "
        "{%0,%1,%2,%3},{%4,%5,%6,%7},{%8,%9},{%0,%1,%2,%3};"
        : "+f"(c[0]), "+f"(c[1]), "+f"(c[2]), "+f"(c[3])
        : "r"(a[0]), "r"(a[1]), "r"(a[2]), "r"(a[3]), "r"(b0), "r"(b1));
}
__device__ __forceinline__ float tanh_fast(float x) {
    x = fminf(fmaxf(x, -15.f), 15.f);
    float e = __expf(2.f * x);
    return __fdividef(e - 1.f, e + 1.f);
}

// ---------------- GEMM (all paths): feat(bf16) = h @ fc_w[p], fused el/er ----------------
__global__ __launch_bounds__(256) void k_gemm(
        const float* __restrict__ h, const float* __restrict__ W,
        const float* __restrict__ al, const float* __restrict__ ar) {
    __shared__ unsigned As[128][33];
    __shared__ unsigned Bs[32][132];
    int tid = threadIdx.x;
    int p = blockIdx.y;
    int row0 = blockIdx.x * 128;
    int w = tid >> 5, t = tid & 31;
    int mrow = (w & 3) * 32;
    int ncol = (w >> 2) * 64;
    const float* Wp = W + (size_t)p * IN_ * HD_;

    float acc[2][8][4];
#pragma unroll
    for (int mf = 0; mf < 2; mf++)
#pragma unroll
        for (int nf = 0; nf < 8; nf++)
#pragma unroll
            for (int k = 0; k < 4; k++) acc[mf][nf][k] = 0.f;

    for (int kk = 0; kk < IN_; kk += 32) {
#pragma unroll
        for (int j = 0; j < 4; j++) {
            int idx = tid + 256 * j;
            int r = idx >> 3;
            int c = (idx & 7) * 4;
            float4 v = make_float4(0.f, 0.f, 0.f, 0.f);
            if (row0 + r < NN)
                v = *(const float4*)&h[(size_t)(row0 + r) * IN_ + kk + c];
            As[r][c] = cvt_tf32(v.x); As[r][c + 1] = cvt_tf32(v.y);
            As[r][c + 2] = cvt_tf32(v.z); As[r][c + 3] = cvt_tf32(v.w);
        }
#pragma unroll
        for (int j = 0; j < 4; j++) {
            int idx = tid + 256 * j;
            int r = idx >> 5;
            int c = (idx & 31) * 4;
            float4 v = *(const float4*)&Wp[(size_t)(kk + r) * HD_ + c];
            Bs[r][c] = cvt_tf32(v.x); Bs[r][c + 1] = cvt_tf32(v.y);
            Bs[r][c + 2] = cvt_tf32(v.z); Bs[r][c + 3] = cvt_tf32(v.w);
        }
        __syncthreads();
#pragma unroll
        for (int ks = 0; ks < 32; ks += 8) {
            unsigned a[2][4];
#pragma unroll
            for (int mf = 0; mf < 2; mf++) {
                int r = mrow + mf * 16 + (t >> 2);
                int kc = ks + (t & 3);
                a[mf][0] = As[r][kc];
                a[mf][1] = As[r + 8][kc];
                a[mf][2] = As[r][kc + 4];
                a[mf][3] = As[r + 8][kc + 4];
            }
#pragma unroll
            for (int nf = 0; nf < 8; nf++) {
                int col = ncol + nf * 8 + (t >> 2);
                int kc = ks + (t & 3);
                unsigned b0 = Bs[kc][col];
                unsigned b1 = Bs[kc + 4][col];
                mma_tf32(acc[0][nf], a[0], b0, b1);
                mma_tf32(acc[1][nf], a[1], b0, b1);
            }
        }
        __syncthreads();
    }

    int headbase = (w >> 2) * 4;
    size_t pn = (size_t)p * NN;
#pragma unroll
    for (int mf = 0; mf < 2; mf++) {
        int ra = row0 + mrow + mf * 16 + (t >> 2);
        int rb = ra + 8;
#pragma unroll
        for (int nf = 0; nf < 8; nf++) {
            int col = ncol + nf * 8 + (t & 3) * 2;
            if (ra < NN)
                *(__nv_bfloat162*)&g_featb[(pn + ra) * HD_ + col] =
                    __float22bfloat162_rn(make_float2(acc[mf][nf][0], acc[mf][nf][1]));
            if (rb < NN)
                *(__nv_bfloat162*)&g_featb[(pn + rb) * HD_ + col] =
                    __float22bfloat162_rn(make_float2(acc[mf][nf][2], acc[mf][nf][3]));
        }
#pragma unroll
        for (int hh = 0; hh < 4; hh++) {
            float sAl = 0.f, sBl = 0.f, sAr = 0.f, sBr = 0.f;
#pragma unroll
            for (int q = 0; q < 2; q++) {
                int nf = hh * 2 + q;
                int col = ncol + nf * 8 + (t & 3) * 2;
                float al0 = al[(size_t)p * HD_ + col], al1 = al[(size_t)p * HD_ + col + 1];
                float ar0 = ar[(size_t)p * HD_ + col], ar1 = ar[(size_t)p * HD_ + col + 1];
                sAl += acc[mf][nf][0] * al0 + acc[mf][nf][1] * al1;
                sBl += acc[mf][nf][2] * al0 + acc[mf][nf][3] * al1;
                sAr += acc[mf][nf][0] * ar0 + acc[mf][nf][1] * ar1;
                sBr += acc[mf][nf][2] * ar0 + acc[mf][nf][3] * ar1;
            }
            sAl += __shfl_xor_sync(0xffffffffu, sAl, 1);
            sAl += __shfl_xor_sync(0xffffffffu, sAl, 2);
            sBl += __shfl_xor_sync(0xffffffffu, sBl, 1);
            sBl += __shfl_xor_sync(0xffffffffu, sBl, 2);
            sAr += __shfl_xor_sync(0xffffffffu, sAr, 1);
            sAr += __shfl_xor_sync(0xffffffffu, sAr, 2);
            sBr += __shfl_xor_sync(0xffffffffu, sBr, 1);
            sBr += __shfl_xor_sync(0xffffffffu, sBr, 2);
            if ((t & 3) == 0) {
                if (ra < NN) {
                    g_el[(pn + ra) * HEADS_ + headbase + hh] = sAl;
                    g_er[(pn + ra) * HEADS_ + headbase + hh] = sAr;
                }
                if (rb < NN) {
                    g_el[(pn + rb) * HEADS_ + headbase + hh] = sBl;
                    g_er[(pn + rb) * HEADS_ + headbase + hh] = sBr;
                }
            }
        }
    }
}

// ---------------- CSR build (whole graph) ----------------
__global__ void k_count(const int* __restrict__ edges) {
    int idx = blockIdx.x * blockDim.x + threadIdx.x;
    if (idx >= MM * EE) return;
    int p = idx / EE, e = idx - p * EE;
    int dst = edges[(size_t)p * 2 * EE + EE + e];
    atomicAdd(&g_deg[p * NN + dst], 1);
}

__global__ __launch_bounds__(1024) void k_scan1() {
    __shared__ int wsum[32];
    int tid = threadIdx.x, lane = tid & 31, wid = tid >> 5;
    int i = blockIdx.x * 1024 + tid;
    int v = (i < NTASK) ? g_deg[i] : 0;
    int x = v;
#pragma unroll
    for (int off = 1; off < 32; off <<= 1) {
        int y = __shfl_up_sync(0xffffffffu, x, off);
        if (lane >= off) x += y;
    }
    if (lane == 31) wsum[wid] = x;
    __syncthreads();
    if (wid == 0) {
        int s = wsum[lane];
#pragma unroll
        for (int off = 1; off < 32; off <<= 1) {
            int y = __shfl_up_sync(0xffffffffu, s, off);
            if (lane >= off) s += y;
        }
        wsum[lane] = s;
    }
    __syncthreads();
    int prefix = (wid ? wsum[wid - 1] : 0) + x - v;
    if (i < NTASK) g_off[i] = prefix;
    if (tid == 1023) g_bsum[blockIdx.x] = wsum[31];
}

__global__ void k_scan2() {
    __shared__ int s[SCAN_BLKS];
    int tid = threadIdx.x;
    if (tid < SCAN_BLKS) s[tid] = g_bsum[tid];
    __syncthreads();
    if (tid == 0) {
        int run = 0;
        for (int k = 0; k < SCAN_BLKS; k++) {
            int t = s[k];
            s[k] = run;
            run += t;
        }
    }
    __syncthreads();
    if (tid < SCAN_BLKS) g_bsum[tid] = s[tid];
}

__global__ __launch_bounds__(1024) void k_scan3() {
    int i = blockIdx.x * 1024 + threadIdx.x;
    if (i < NTASK) {
        int o = g_off[i] + g_bsum[blockIdx.x];
        g_off[i] = o;
        g_cur[i] = o;
    }
}

__global__ void k_scatter(const int* __restrict__ edges) {
    int idx = blockIdx.x * blockDim.x + threadIdx.x;
    if (idx >= MM * EE) return;
    int p = idx / EE, e = idx - p * EE;
    const int* eb = edges + (size_t)p * 2 * EE;
    int src = eb[e], dst = eb[EE + e];
    int pos = atomicAdd(&g_cur[p * NN + dst], 1);
    g_csr[pos] = src;
}

// ------- fused edge softmax + aggregation + elu: single-pass, no smem -------
// warp per (path,node). Lane owns head hB=lane>>2, dims 4*lane..4*lane+3.
// All 4 lanes of a quad compute identical ex/s (redundant MUFU, zero sync).
__global__ __launch_bounds__(256) void k_agg() {
    int warp = threadIdx.x >> 5, lane = threadIdx.x & 31;
    int t = blockIdx.x * 8 + warp;
    if (t >= NTASK) return;
    int p = t / NN;
    int deg = g_deg[t];
    int base = g_off[t];

    if (deg == 0) {
        *(float4*)&g_z[(size_t)t * HD_ + lane * 4] = make_float4(0.f, 0.f, 0.f, 0.f);
        return;
    }

    int hB = lane >> 2;
    float er_h = g_er[(size_t)t * HEADS_ + hB];
    size_t pnn = (size_t)p * NN;

    float s = 0.f;
    float4 acc = make_float4(0.f, 0.f, 0.f, 0.f);

#pragma unroll 4
    for (int e = 0; e < deg; e++) {
        int src = g_csr[base + e];
        float v = g_el[(pnn + src) * HEADS_ + hB] + er_h;
        v = v > 0.f ? v : 0.2f * v;
        float ex = __expf(v);
        s += ex;
        uint2 fv = *(const uint2*)&g_featb[(pnn + src) * HD_ + lane * 4];
        float2 f0 = __bfloat1622float2(*reinterpret_cast<__nv_bfloat162*>(&fv.x));
        float2 f1 = __bfloat1622float2(*reinterpret_cast<__nv_bfloat162*>(&fv.y));
        acc.x += ex * f0.x; acc.y += ex * f0.y;
        acc.z += ex * f1.x; acc.w += ex * f1.y;
    }

    float inv = 1.f / s;
    float zx = acc.x * inv, zy = acc.y * inv, zz = acc.z * inv, zw = acc.w * inv;
    zx = zx > 0.f ? zx : expm1f(zx);
    zy = zy > 0.f ? zy : expm1f(zy);
    zz = zz > 0.f ? zz : expm1f(zz);
    zw = zw > 0.f ? zw : expm1f(zw);
    *(float4*)&g_z[(size_t)t * HD_ + lane * 4] = make_float4(zx, zy, zz, zw);
}

// ------- fused structure attention + node-softmax accumulation (all paths) -------
__global__ __launch_bounds__(256) void k_wbeta(
        const float* __restrict__ W1, const float* __restrict__ b1,
        const float* __restrict__ w2) {
    __shared__ unsigned As[128][33];
    __shared__ unsigned Bs[32][132];
    __shared__ float sw[128][2];
    __shared__ float spv[128];
    int mpath = blockIdx.y;
    int row0 = blockIdx.x * 128;
    int tid = threadIdx.x;
    int w = tid >> 5, t = tid & 31;
    int mrow = (w & 3) * 32;
    int ncol = (w >> 2) * 64;
    int half = w >> 2;

    float acc[2][8][4];
#pragma unroll
    for (int nf = 0; nf < 8; nf++) {
        int col = ncol + nf * 8 + (t & 3) * 2;
        float b0 = b1[col], b1v = b1[col + 1];
#pragma unroll
        for (int mf = 0; mf < 2; mf++) {
            acc[mf][nf][0] = b0; acc[mf][nf][1] = b1v;
            acc[mf][nf][2] = b0; acc[mf][nf][3] = b1v;
        }
    }

    for (int kk = 0; kk < HD_; kk += 32) {
#pragma unroll
        for (int j = 0; j < 4; j++) {
            int idx = tid + 256 * j;
            int r = idx >> 3;
            int c = (idx & 7) * 4;
            float4 v = make_float4(0.f, 0.f, 0.f, 0.f);
            if (row0 + r < NN)
                v = *(const float4*)&g_z[((size_t)mpath * NN + row0 + r) * HD_ + kk + c];
            As[r][c] = cvt_tf32(v.x); As[r][c + 1] = cvt_tf32(v.y);
            As[r][c + 2] = cvt_tf32(v.z); As[r][c + 3] = cvt_tf32(v.w);
        }
#pragma unroll
        for (int j = 0; j < 4; j++) {
            int idx = tid + 256 * j;
            int r = idx >> 5;
            int c = (idx & 31) * 4;
            float4 v = *(const float4*)&W1[(size_t)(kk + r) * HD_ + c];
            Bs[r][c] = cvt_tf32(v.x); Bs[r][c + 1] = cvt_tf32(v.y);
            Bs[r][c + 2] = cvt_tf32(v.z); Bs[r][c + 3] = cvt_tf32(v.w);
        }
        __syncthreads();
#pragma unroll
        for (int ks = 0; ks < 32; ks += 8) {
            unsigned a[2][4];
#pragma unroll
            for (int mf = 0; mf < 2; mf++) {
                int r = mrow + mf * 16 + (t >> 2);
                int kc = ks + (t & 3);
                a[mf][0] = As[r][kc];
                a[mf][1] = As[r + 8][kc];
                a[mf][2] = As[r][kc + 4];
                a[mf][3] = As[r + 8][kc + 4];
            }
#pragma unroll
            for (int nf = 0; nf < 8; nf++) {
                int col = ncol + nf * 8 + (t >> 2);
                int kc = ks + (t & 3);
                unsigned b0 = Bs[kc][col];
                unsigned b1f = Bs[kc + 4][col];
                mma_tf32(acc[0][nf], a[0], b0, b1f);
                mma_tf32(acc[1][nf], a[1], b0, b1f);
            }
        }
        __syncthreads();
    }

#pragma unroll
    for (int mf = 0; mf < 2; mf++) {
        int lra = mrow + mf * 16 + (t >> 2);
        float tA = 0.f, tB = 0.f;
#pragma unroll
        for (int nf = 0; nf < 8; nf++) {
            int col = ncol + nf * 8 + (t & 3) * 2;
            float w0 = w2[col], w1v = w2[col + 1];
            tA += tanh_fast(acc[mf][nf][0]) * w0 + tanh_fast(acc[mf][nf][1]) * w1v;
            tB += tanh_fast(acc[mf][nf][2]) * w0 + tanh_fast(acc[mf][nf][3]) * w1v;
        }
        tA += __shfl_xor_sync(0xffffffffu, tA, 1);
        tA += __shfl_xor_sync(0xffffffffu, tA, 2);
        tB += __shfl_xor_sync(0xffffffffu, tB, 1);
        tB += __shfl_xor_sync(0xffffffffu, tB, 2);
        if ((t & 3) == 0) {
            sw[lra][half] = tA;
            sw[lra + 8][half] = tB;
        }
    }
    __syncthreads();
    if (tid < 128) {
        float wv = sw[tid][0] + sw[tid][1];
        spv[tid] = (row0 + tid < NN) ? __expf(wv) : 0.f;
    }
    __syncthreads();

    float4 a4 = make_float4(0.f, 0.f, 0.f, 0.f);
    float ws = 0.f;
#pragma unroll
    for (int r = 0; r < 16; r++) {
        int lr = w * 16 + r;
        int gr = row0 + lr;
        float pv = spv[lr];
        if (gr < NN) {
            float4 zv = *(const float4*)&g_z[((size_t)mpath * NN + gr) * HD_ + t * 4];
            a4.x += pv * zv.x; a4.y += pv * zv.y;
            a4.z += pv * zv.z; a4.w += pv * zv.w;
            ws += pv;
        }
    }
    float* o = &g_pz[mpath * HD_ + t * 4];
    asm volatile("red.global.add.v4.f32 [%0], {%1,%2,%3,%4};"
                 :: "l"(o), "f"(a4.x), "f"(a4.y), "f"(a4.z), "f"(a4.w)
                 : "memory");
    if (t == 0) atomicAdd(&g_wsum[mpath], ws);
}

__global__ void k_final(const float* __restrict__ pred_w, const float* __restrict__ pred_b,
                        float* __restrict__ out) {
    int t = threadIdx.x;
    if (t < MM * OUT_) {
        int m = t / OUT_, o = t - m * OUT_;
        float inv = 1.f / g_wsum[m];
        float s = pred_b[o];
#pragma unroll 8
        for (int j = 0; j < HD_; j++)
            s += g_pz[m * HD_ + j] * inv * pred_w[(size_t)j * OUT_ + o];
        out[t] = s;
    }
}

// ---------------- launch (R7 skeleton: CSR chain on s2 || GEMM on main) ----------------
extern "C" void kernel_launch(void* const* d_in, const int* in_sizes, int n_in,
                              void* d_out, int out_size) {
    const float* h      = (const float*)d_in[0];
    const int*   edges  = (const int*)d_in[1];
    const float* fc_w   = (const float*)d_in[2];
    const float* attn_l = (const float*)d_in[3];
    const float* attn_r = (const float*)d_in[4];
    const float* sa_w1  = (const float*)d_in[5];
    const float* sa_b1  = (const float*)d_in[6];
    const float* sa_w2  = (const float*)d_in[7];
    const float* pred_w = (const float*)d_in[8];
    const float* pred_b = (const float*)d_in[9];
    float* out = (float*)d_out;

    void *pdeg, *pwsum, *ppz;
    cudaGetSymbolAddress(&pdeg, g_deg);
    cudaGetSymbolAddress(&pwsum, g_wsum);
    cudaGetSymbolAddress(&ppz, g_pz);

    cudaStream_t s2;
    cudaStreamCreateWithFlags(&s2, cudaStreamNonBlocking);
    cudaEvent_t evFork, evJoin;
    cudaEventCreateWithFlags(&evFork, cudaEventDisableTiming);
    cudaEventCreateWithFlags(&evJoin, cudaEventDisableTiming);

    // fork: whole-graph CSR chain on s2, overlapping gemm on main
    cudaEventRecord(evFork, 0);
    cudaStreamWaitEvent(s2, evFork, 0);

    cudaMemsetAsync(pdeg, 0, sizeof(int) * NTASK, s2);
    int et = MM * EE;
    k_count<<<(et + 255) / 256, 256, 0, s2>>>(edges);
    k_scan1<<<SCAN_BLKS, 1024, 0, s2>>>();
    k_scan2<<<1, 256, 0, s2>>>();
    k_scan3<<<SCAN_BLKS, 1024, 0, s2>>>();
    k_scatter<<<(et + 255) / 256, 256, 0, s2>>>(edges);
    cudaEventRecord(evJoin, s2);

    // main: memsets + gemm
    cudaMemsetAsync(pwsum, 0, sizeof(float) * MM);
    cudaMemsetAsync(ppz, 0, sizeof(float) * MM * HD_);
    dim3 gg(GEMM_BLKS, MM);
    k_gemm<<<gg, 256>>>(h, fc_w, attn_l, attn_r);

    // join, then dependent tail
    cudaStreamWaitEvent(0, evJoin, 0);
    k_agg<<<(NTASK + 7) / 8, 256>>>();
    k_wbeta<<<gg, 256>>>(sa_w1, sa_b1, sa_w2);
    k_final<<<1, 32>>>(pred_w, pred_b, out);

    cudaEventDestroy(evFork);
    cudaEventDestroy(evJoin);
    cudaStreamDestroy(s2);
}